// round 8
// baseline (speedup 1.0000x reference)
#include <cuda_runtime.h>
#include <stdint.h>

// Problem constants (fixed by the dataset)
#define BB   16
#define NN   2048
#define CC   256
#define KK   16
#define KP1  17
#define OUTC 259   // 3 + C

// Scratch for knn indices (device global: allocation-free)
__device__ int g_knn[BB * NN * KK];

// order-preserving fp32 <-> u32 maps
__device__ __forceinline__ unsigned f2u(float f) {
    unsigned u = __float_as_uint(f);
    return u ^ (((unsigned)((int)u >> 31)) | 0x80000000u);
}
__device__ __forceinline__ float u2f(unsigned u) {
    unsigned v = u ^ (((unsigned)((int)(~u) >> 31)) | 0x80000000u);
    return __uint_as_float(v);
}

// ---------------------------------------------------------------------------
// Kernel A: warp-per-query exact top-17.
// The 17 best (key = u32 sortable d2, payload = idx) live one-per-lane on
// lanes 0..16. Lanes scan 32 candidates per step; ballot of "beats current
// 17th" (FLOAT compare vs maxf — f2u only on the rare insert path) processed
// serially in ascending m, warp-uniform. Eviction: among holders with
// key == max, evict largest idx (top_k tie semantics); strict accept keeps
// the incumbent on boundary ties. (key, idx) pairs unique -> single eviction.
// Sentinels 0xFF7FF00|lane decode to DISTINCT FINITE floats (~FLT_MAX), so
// maxf is a real number from the start (R7 bug: 0xFFFFFF00 -> NaN).
// ---------------------------------------------------------------------------
#define QW 8   // query warps per block (256 threads)
__global__ __launch_bounds__(256)
void knn_kernel(const float* __restrict__ xyz, float* __restrict__ out)
{
    __shared__ float4 sp[NN];   // 32 KB: x, y, z, |p|^2

    const int b    = blockIdx.y;
    const int tid  = threadIdx.x;
    const int lane = tid & 31;
    const int warp = tid >> 5;
    const float* xb = xyz + (size_t)b * NN * 3;

    for (int m = tid; m < NN; m += 256) {
        float x = xb[m * 3 + 0];
        float y = xb[m * 3 + 1];
        float z = xb[m * 3 + 2];
        sp[m] = make_float4(x, y, z, x * x + y * y + z * z);
    }
    __syncthreads();

    const int n = blockIdx.x * QW + warp;     // this warp's query
    const float4 q = sp[n];

    const bool holder = (lane < KP1);
    // distinct FINITE sentinels: u2f(0xFF7FFF00|i) ~ 3.4e38, real keys << this
    unsigned ku   = holder ? (0xFF7FFF00u | (unsigned)lane) : 0u;
    unsigned kidx = 0u;
    unsigned maxu = 0xFF7FFF00u | (KP1 - 1);  // current 17th (max over holders)
    float    maxf = u2f(maxu);                // finite, ~FLT_MAX

    for (int step = 0; step < NN / 32; step++) {
        const int m = step * 32 + lane;
        float4 p = sp[m];                     // LDS.128, conflict-free
        float dot = q.x * p.x + q.y * p.y + q.z * p.z;
        float d2  = q.w + p.w - 2.0f * dot;   // same formula as reference

        unsigned bal = __ballot_sync(0xffffffffu, d2 < maxf);
        while (bal) {                         // warp-uniform loop
            const int src = __ffs(bal) - 1;
            bal &= bal - 1;
            float cf = __shfl_sync(0xffffffffu, d2, src);
            if (cf < maxf) {                  // strict: boundary tie -> reject
                unsigned cu = f2u(cf);
                unsigned cm = (unsigned)(step * 32 + src);
                // evict: among holders with ku==maxu, the largest kidx
                bool ismax = holder && (ku == maxu);
                unsigned emx = __reduce_max_sync(0xffffffffu, ismax ? kidx : 0u);
                if (ismax && kidx == emx) { ku = cu; kidx = cm; }
                maxu = __reduce_max_sync(0xffffffffu, holder ? ku : 0u);
                maxf = u2f(maxu);
            }
        }
    }

    // identify self = min key, lowest idx among exact ties (sorted column 0)
    unsigned minu = __reduce_min_sync(0xffffffffu, holder ? ku : 0xFFFFFFFFu);
    bool ismin = holder && (ku == minu);
    unsigned mni = __reduce_min_sync(0xffffffffu, ismin ? kidx : 0xFFFFFFFFu);
    bool keep = holder && !(ismin && kidx == mni);

    // mean of neighbor xyz (16 keepers)
    float4 pN = make_float4(0.f, 0.f, 0.f, 0.f);
    if (keep) pN = sp[kidx];
    float sx = pN.x, sy = pN.y, sz = pN.z;
#pragma unroll
    for (int o = 16; o > 0; o >>= 1) {
        sx += __shfl_xor_sync(0xffffffffu, sx, o);
        sy += __shfl_xor_sync(0xffffffffu, sy, o);
        sz += __shfl_xor_sync(0xffffffffu, sz, o);
    }
    if (lane == 0) {
        const float inv = 1.0f / (float)KK;
        size_t ob = ((size_t)b * NN + n) * OUTC;
        out[ob + 0] = sx * inv - q.x;
        out[ob + 1] = sy * inv - q.y;
        out[ob + 2] = sz * inv - q.z;
    }

    // emit knn indices (order within row irrelevant: gather sums them)
    unsigned kb = __ballot_sync(0xffffffffu, keep);
    int pos = __popc(kb & ((1u << lane) - 1u));
    if (keep) g_knn[((size_t)b * NN + n) * KK + pos] = (int)kidx;
}

// ---------------------------------------------------------------------------
// Kernel B: feature gather + mean - self.
// Block = (16-channel tile, batch), 1024 threads (32 warps -> ~50% occ).
// SMEM rows padded to 2049: the 16 channel lanes of a group read banks
// (c + idx) % 32 — conflict-free within the group.
// ---------------------------------------------------------------------------
#define CT    16
#define PITCH 2049
#define SMEMB (CT * PITCH * (int)sizeof(float))

__global__ __launch_bounds__(1024)
void gather_kernel(const float* __restrict__ features, float* __restrict__ out)
{
    extern __shared__ float fsm[];   // [CT][PITCH]

    const int b   = blockIdx.y;
    const int c0  = blockIdx.x * CT;
    const int tid = threadIdx.x;

    // Stage 16 channel rows (contiguous gmem) into padded SMEM rows
    const float* fb = features + ((size_t)b * CC + c0) * NN;
    for (int i = tid; i < CT * NN; i += 1024) {
        int c = i >> 11;          // / NN
        int m = i & (NN - 1);
        fsm[c * PITCH + m] = fb[i];
    }
    __syncthreads();

    const int c  = tid & 15;
    const int n0 = tid >> 4;      // 0..63

    const int*   knn_b = g_knn + (size_t)b * NN * KK;
    const float* frow  = fsm + c * PITCH;
    float* outc = out + (size_t)b * NN * OUTC + 3 + c0 + c;

#pragma unroll 2
    for (int n = n0; n < NN; n += 64) {
        const int4* kr = (const int4*)(knn_b + n * KK);
        int4 k0 = __ldg(kr + 0);
        int4 k1 = __ldg(kr + 1);
        int4 k2 = __ldg(kr + 2);
        int4 k3 = __ldg(kr + 3);

        float s = frow[k0.x] + frow[k0.y] + frow[k0.z] + frow[k0.w]
                + frow[k1.x] + frow[k1.y] + frow[k1.z] + frow[k1.w]
                + frow[k2.x] + frow[k2.y] + frow[k2.z] + frow[k2.w]
                + frow[k3.x] + frow[k3.y] + frow[k3.z] + frow[k3.w];

        outc[(size_t)n * OUTC] = s * (1.0f / (float)KK) - frow[n];
    }
}

// ---------------------------------------------------------------------------
extern "C" void kernel_launch(void* const* d_in, const int* in_sizes, int n_in,
                              void* d_out, int out_size)
{
    const float* xyz      = (const float*)d_in[0];
    const float* features = (const float*)d_in[1];
    float* out = (float*)d_out;

    knn_kernel<<<dim3(NN / QW, BB), 256>>>(xyz, out);

    cudaFuncSetAttribute(gather_kernel,
                         cudaFuncAttributeMaxDynamicSharedMemorySize, SMEMB);
    gather_kernel<<<dim3(CC / CT, BB), 1024, SMEMB>>>(features, out);
}

// round 10
// speedup vs baseline: 1.2774x; 1.2774x over previous
#include <cuda_runtime.h>
#include <cuda_fp16.h>
#include <stdint.h>

// Problem constants (fixed by the dataset)
#define BB   16
#define NN   2048
#define CC   256
#define KK   16
#define KP1  17
#define OUTC 259   // 3 + C

// Scratch for knn indices (device global: allocation-free)
__device__ int g_knn[BB * NN * KK];

// order-preserving fp32 -> u32 map
__device__ __forceinline__ unsigned f2u(float f) {
    unsigned u = __float_as_uint(f);
    return u ^ (((unsigned)((int)u >> 31)) | 0x80000000u);
}

// ---------------------------------------------------------------------------
// Kernel A: warp-per-query exact top-17  (R5 version — u-space scan compare;
// measured faster than the float-compare variant).
// 17 best (key = u32 sortable d2, payload = idx) live one-per-lane on lanes
// 0..16. Lanes scan 32 candidates/step; ballot of "beats current 17th"
// processed serially in ascending m (warp-uniform). Eviction: among holders
// with key == max, evict largest idx (top_k tie semantics); strict accept
// keeps incumbents on boundary ties. (key, idx) unique -> single eviction.
// ---------------------------------------------------------------------------
#define QW 8   // query warps per block (256 threads)
__global__ __launch_bounds__(256)
void knn_kernel(const float* __restrict__ xyz, float* __restrict__ out)
{
    __shared__ float4 sp[NN];   // 32 KB: x, y, z, |p|^2

    const int b    = blockIdx.y;
    const int tid  = threadIdx.x;
    const int lane = tid & 31;
    const int warp = tid >> 5;
    const float* xb = xyz + (size_t)b * NN * 3;

    for (int m = tid; m < NN; m += 256) {
        float x = xb[m * 3 + 0];
        float y = xb[m * 3 + 1];
        float z = xb[m * 3 + 2];
        sp[m] = make_float4(x, y, z, x * x + y * y + z * z);
    }
    __syncthreads();

    const int n = blockIdx.x * QW + warp;     // this warp's query
    const float4 q = sp[n];

    const bool holder = (lane < KP1);
    // distinct huge sentinels (real u keys are far below 0xFFFFFF00)
    unsigned ku   = holder ? (0xFFFFFF00u | (unsigned)lane) : 0u;
    unsigned kidx = 0u;
    unsigned maxu = 0xFFFFFF00u | (KP1 - 1);  // current 17th (max of holders)

    for (int step = 0; step < NN / 32; step++) {
        const int m = step * 32 + lane;
        float4 p = sp[m];                     // LDS.128, conflict-free
        float dot = q.x * p.x + q.y * p.y + q.z * p.z;
        float d2  = q.w + p.w - 2.0f * dot;   // same formula as reference
        unsigned u = f2u(d2);

        unsigned bal = __ballot_sync(0xffffffffu, u < maxu);
        while (bal) {                         // warp-uniform loop
            const int src = __ffs(bal) - 1;
            bal &= bal - 1;
            unsigned cu = __shfl_sync(0xffffffffu, u, src);
            unsigned cm = (unsigned)(step * 32 + src);
            if (cu < maxu) {                  // strict: boundary tie -> reject
                // evict: among holders with ku==maxu, the largest kidx
                bool ismax = holder && (ku == maxu);
                unsigned emx = __reduce_max_sync(0xffffffffu, ismax ? kidx : 0u);
                if (ismax && kidx == emx) { ku = cu; kidx = cm; }
                maxu = __reduce_max_sync(0xffffffffu, holder ? ku : 0u);
            }
        }
    }

    // identify self = min key, lowest idx among exact ties (sorted column 0)
    unsigned minu = __reduce_min_sync(0xffffffffu, holder ? ku : 0xFFFFFFFFu);
    bool ismin = holder && (ku == minu);
    unsigned mni = __reduce_min_sync(0xffffffffu, ismin ? kidx : 0xFFFFFFFFu);
    bool keep = holder && !(ismin && kidx == mni);

    // mean of neighbor xyz (16 keepers)
    float4 pN = make_float4(0.f, 0.f, 0.f, 0.f);
    if (keep) pN = sp[kidx];
    float sx = pN.x, sy = pN.y, sz = pN.z;
#pragma unroll
    for (int o = 16; o > 0; o >>= 1) {
        sx += __shfl_xor_sync(0xffffffffu, sx, o);
        sy += __shfl_xor_sync(0xffffffffu, sy, o);
        sz += __shfl_xor_sync(0xffffffffu, sz, o);
    }
    if (lane == 0) {
        const float inv = 1.0f / (float)KK;
        size_t ob = ((size_t)b * NN + n) * OUTC;
        out[ob + 0] = sx * inv - q.x;
        out[ob + 1] = sy * inv - q.y;
        out[ob + 2] = sz * inv - q.z;
    }

    // emit knn indices (order within row irrelevant: gather sums them)
    unsigned kb = __ballot_sync(0xffffffffu, keep);
    int pos = __popc(kb & ((1u << lane) - 1u));
    if (keep) g_knn[((size_t)b * NN + n) * KK + pos] = (int)kidx;
}

// ---------------------------------------------------------------------------
// Kernel B: feature gather + mean - self, fp16x2 channel pairing.
// Block covers 32 channels: SMEM row c (0..15) holds half2(ch c0+c, ch c0+c+16)
// for all 2048 points, pitch 2049 (4B units) -> the 16 channel lanes of a
// group hit banks (c + idx) % 32, conflict-free. One LDS gather feeds TWO
// output channels -> half the L1 work per channel vs fp32 tiling.
// fp16 storage error ~2e-4 RMS vs output magnitude ~1.0 (well under budget).
// ---------------------------------------------------------------------------
#define CTP    32           // channels per block (16 half2 rows)
#define PITCH  2049
#define SMEMB  (16 * PITCH * (int)sizeof(__half2))

__global__ __launch_bounds__(1024)
void gather_kernel(const float* __restrict__ features, float* __restrict__ out)
{
    extern __shared__ __half2 fsm[];   // [16][PITCH]

    const int b   = blockIdx.y;
    const int c0  = blockIdx.x * CTP;
    const int tid = threadIdx.x;

    // Stage: pack channels (c0+c, c0+c+16) as half2 rows
    const float* fbase = features + ((size_t)b * CC + c0) * NN;
    for (int i = tid; i < 16 * NN; i += 1024) {
        int c = i >> 11;          // 0..15
        int m = i & (NN - 1);
        float v0 = fbase[(size_t)c * NN + m];
        float v1 = fbase[(size_t)(c + 16) * NN + m];
        fsm[c * PITCH + m] = __floats2half2_rn(v0, v1);
    }
    __syncthreads();

    const int c  = tid & 15;      // half2 row
    const int n0 = tid >> 4;      // 0..63

    const int*     knn_b = g_knn + (size_t)b * NN * KK;
    const __half2* frow  = fsm + c * PITCH;
    float* outc = out + (size_t)b * NN * OUTC + 3 + c0 + c;

#pragma unroll 2
    for (int n = n0; n < NN; n += 64) {
        const int4* kr = (const int4*)(knn_b + n * KK);
        int4 k0 = __ldg(kr + 0);
        int4 k1 = __ldg(kr + 1);
        int4 k2 = __ldg(kr + 2);
        int4 k3 = __ldg(kr + 3);

        float2 a0 = __half22float2(frow[k0.x]);
        float2 a1 = __half22float2(frow[k0.y]);
        float2 a2 = __half22float2(frow[k0.z]);
        float2 a3 = __half22float2(frow[k0.w]);
        float2 a4 = __half22float2(frow[k1.x]);
        float2 a5 = __half22float2(frow[k1.y]);
        float2 a6 = __half22float2(frow[k1.z]);
        float2 a7 = __half22float2(frow[k1.w]);
        float s0 = a0.x + a1.x + a2.x + a3.x + a4.x + a5.x + a6.x + a7.x;
        float s1 = a0.y + a1.y + a2.y + a3.y + a4.y + a5.y + a6.y + a7.y;
        a0 = __half22float2(frow[k2.x]);
        a1 = __half22float2(frow[k2.y]);
        a2 = __half22float2(frow[k2.z]);
        a3 = __half22float2(frow[k2.w]);
        a4 = __half22float2(frow[k3.x]);
        a5 = __half22float2(frow[k3.y]);
        a6 = __half22float2(frow[k3.z]);
        a7 = __half22float2(frow[k3.w]);
        s0 += a0.x + a1.x + a2.x + a3.x + a4.x + a5.x + a6.x + a7.x;
        s1 += a0.y + a1.y + a2.y + a3.y + a4.y + a5.y + a6.y + a7.y;

        float2 self = __half22float2(frow[n]);
        float* o = outc + (size_t)n * OUTC;
        o[0]  = s0 * (1.0f / (float)KK) - self.x;
        o[16] = s1 * (1.0f / (float)KK) - self.y;
    }
}

// ---------------------------------------------------------------------------
extern "C" void kernel_launch(void* const* d_in, const int* in_sizes, int n_in,
                              void* d_out, int out_size)
{
    const float* xyz      = (const float*)d_in[0];
    const float* features = (const float*)d_in[1];
    float* out = (float*)d_out;

    knn_kernel<<<dim3(NN / QW, BB), 256>>>(xyz, out);

    cudaFuncSetAttribute(gather_kernel,
                         cudaFuncAttributeMaxDynamicSharedMemorySize, SMEMB);
    gather_kernel<<<dim3(CC / CTP, BB), 1024, SMEMB>>>(features, out);
}